// round 12
// baseline (speedup 1.0000x reference)
#include <cuda_runtime.h>

#define NWORDS 100000
#define NQ 50
#define NS 64
#define NBLOCKS 391   // ceil(100000 / 256)

// Heads table, padded octant layout: per (q, qt) cell of 28 floats (112B stride)
__device__ __align__(16) float g_hH[NQ * 8 * 28];
__device__ __align__(8)  float g_hr[NS];
__device__ double g_acc = 0.0;
__device__ unsigned int g_counter = 0u;

typedef unsigned long long u64;

__device__ __forceinline__ u64 bc2(float x) {
    u64 r; asm("mov.b64 %0, {%1, %1};" : "=l"(r) : "f"(x)); return r;
}
__device__ __forceinline__ u64 fma2(u64 a, u64 b, u64 c) {
    u64 d; asm("fma.rn.f32x2 %0, %1, %2, %3;" : "=l"(d) : "l"(a), "l"(b), "l"(c)); return d;
}
__device__ __forceinline__ u64 mul2(u64 a, u64 b) {
    u64 d; asm("mul.rn.f32x2 %0, %1, %2;" : "=l"(d) : "l"(a), "l"(b)); return d;
}
__device__ __forceinline__ void up2(u64 a, float& x, float& y) {
    asm("mov.b64 {%0, %1}, %2;" : "=f"(x), "=f"(y) : "l"(a));
}

__device__ __forceinline__ float sp20(float x) {
    float y = 20.0f * x;
    return fmaxf(y, 0.0f) + log1pf(expf(-fabsf(y)));
}

__global__ void setup_kernel(const float* __restrict__ hp, const float* __restrict__ hrp) {
    int tid = threadIdx.x;
    if (blockIdx.x == 0) {
        __shared__ float sv[NS];
        __shared__ float ssum;
        if (tid < NS) sv[tid] = sp20(hrp[tid]);
        __syncthreads();
        if (tid == 0) {
            float s = 0.0f;
            for (int i = 0; i < NS; i++) s += sv[i];
            ssum = fmaxf(s, 1e-12f);
        }
        __syncthreads();
        if (tid < NS) g_hr[tid] = (sv[tid] / ssum + 0.001f / (float)NS) / 1.001f;
    }
    int idx = blockIdx.x * blockDim.x + tid;
    if (idx < NS * NQ) {
        int q = idx >> 6;
        int s = idx & 63;
        const float* p = hp + ((size_t)s * NQ + q) * 3;
        float v0 = sp20(p[0]);
        float v1 = sp20(p[1]);
        float v2 = sp20(p[2]);
        float sm = fmaxf((v0 + v1) + v2, 1e-12f);
        int qt = s >> 3, j = (s >> 2) & 1, r = s & 3;
        float* g = g_hH + ((size_t)q * 8 + qt) * 28 + j * 12;
        g[r]     = v0 / sm;
        g[4 + r] = v1 / sm;
        g[8 + r] = v2 / sm;
    }
}

// Thread = (n-octet, s-octant). 256 threads -> 32 n-octets (256 n) x 8 s-octants.
// smem: heads 11200 f (44.8KB) + tile 30 rows x pitch 292 (swizzle fits: 28+255<292)
#define SH_HEADS 11200
#define SH_TROW  292
#define SH_TILE  (30 * SH_TROW + 32)
#define SMEM_FLOATS (SH_HEADS + SH_TILE)

// per-row 16B swizzle keeps staging STS ~2-way instead of 4-way:
#define TROW_OFF(r) ((r) * SH_TROW + 4 * (((r) >> 1) & 7))

__global__ __launch_bounds__(256, 2)
void cov_kernel(const float* __restrict__ tpl, const float* __restrict__ coeff,
                float* __restrict__ out) {
    extern __shared__ __align__(16) float smem[];
    float* sH = smem;
    float* sT = smem + SH_HEADS;

    const int tid   = threadIdx.x;
    const int qt    = tid & 7;          // s-octant 0..7 (8 heads each)
    const int nq    = tid >> 3;         // n-octet 0..31
    const int nBase = blockIdx.x * 256;

    // stage heads table (44.8 KB) once per block
    {
        const float4* src = (const float4*)g_hH;
        float4* dst = (float4*)sH;
        for (int i = tid; i < SH_HEADS / 4; i += 256) dst[i] = src[i];
    }

    const u64 ONE = 0x3f8000003f800000ULL;
    u64 prod[4][8];
#pragma unroll
    for (int p = 0; p < 4; p++)
#pragma unroll
        for (int n = 0; n < 8; n++) prod[p][n] = ONE;

#pragma unroll 1
    for (int qc = 0; qc < NQ; qc += 10) {
        __syncthreads();   // heads staging (1st iter) / sT reuse
        // stage 256 rows x 30 floats (coalesced float2) -> transposed, swizzled sT
        for (int i = tid; i < 256 * 15; i += 256) {
            int nl = i / 15;
            int j2 = i - nl * 15;
            int n  = nBase + nl;
            n = (n < NWORDS) ? n : (NWORDS - 1);
            float2 v = *(const float2*)(tpl + (size_t)n * (NQ * 3) + (size_t)(qc * 3 + j2 * 2));
            int jj = j2 * 2;
            int sw = 4 * (j2 & 7);
            sT[jj * SH_TROW + sw + nl]       = v.x;
            sT[(jj + 1) * SH_TROW + sw + nl] = v.y;
        }
        __syncthreads();

#pragma unroll 1
        for (int qq = 0; qq < 10; qq++) {
            // conflict-free heads cell (112B stride across octant lanes)
            const ulonglong2* hb =
                (const ulonglong2*)(sH + ((size_t)(qc + qq) * 8 + qt) * 28);
            ulonglong2 A0 = hb[0], B0 = hb[1], C0 = hb[2];
            ulonglong2 A1 = hb[3], B1 = hb[4], C1 = hb[5];

            int r0 = qq * 3, r1 = r0 + 1, r2 = r0 + 2;
            const float* t0 = sT + TROW_OFF(r0) + nq * 8;
            const float* t1 = sT + TROW_OFF(r1) + nq * 8;
            const float* t2 = sT + TROW_OFF(r2) + nq * 8;
            float4 a0 = *(const float4*)t0, a1 = *(const float4*)(t0 + 4);
            float4 b0 = *(const float4*)t1, b1 = *(const float4*)(t1 + 4);
            float4 c0 = *(const float4*)t2, c1 = *(const float4*)(t2 + 4);
            float v0[8] = {a0.x, a0.y, a0.z, a0.w, a1.x, a1.y, a1.z, a1.w};
            float v1[8] = {b0.x, b0.y, b0.z, b0.w, b1.x, b1.y, b1.z, b1.w};
            float v2[8] = {c0.x, c0.y, c0.z, c0.w, c1.x, c1.y, c1.z, c1.w};

#pragma unroll
            for (int n = 0; n < 8; n++) {
                u64 T0 = bc2(v0[n]);
                u64 T1 = bc2(v1[n]);
                u64 T2 = bc2(v2[n]);
                u64 a = mul2(C0.x, T2);
                a = fma2(B0.x, T1, a);
                a = fma2(A0.x, T0, a);
                prod[0][n] = mul2(prod[0][n], a);
                u64 b = mul2(C0.y, T2);
                b = fma2(B0.y, T1, b);
                b = fma2(A0.y, T0, b);
                prod[1][n] = mul2(prod[1][n], b);
                u64 c = mul2(C1.x, T2);
                c = fma2(B1.x, T1, c);
                c = fma2(A1.x, T0, c);
                prod[2][n] = mul2(prod[2][n], c);
                u64 d = mul2(C1.y, T2);
                d = fma2(B1.y, T1, d);
                d = fma2(A1.y, T0, d);
                prod[3][n] = mul2(prod[3][n], d);
            }
        }
    }

    // ratio-weighted partial covs for this thread's 8 n over its 8 heads
    float cov[8] = {0.f, 0.f, 0.f, 0.f, 0.f, 0.f, 0.f, 0.f};
#pragma unroll
    for (int p = 0; p < 4; p++) {
        float2 w = *(const float2*)(g_hr + (size_t)qt * 8 + p * 2);
#pragma unroll
        for (int n = 0; n < 8; n++) {
            float lo, hi;
            up2(prod[p][n], lo, hi);
            cov[n] = fmaf(w.x, lo, cov[n]);
            cov[n] = fmaf(w.y, hi, cov[n]);
        }
    }
    // combine the 8 s-octants (8 consecutive lanes share an n-octet)
#pragma unroll
    for (int o = 1; o <= 4; o <<= 1)
#pragma unroll
        for (int n = 0; n < 8; n++)
            cov[n] += __shfl_xor_sync(0xffffffffu, cov[n], o);

    double term = 0.0;
    if (qt == 0) {
        int n0 = nBase + nq * 8;
#pragma unroll
        for (int k = 0; k < 8; k++) {
            if (n0 + k < NWORDS) {
                float c = coeff[n0 + k];
                term += ((double)c * (double)c) / (double)cov[k];
            }
        }
    }
#pragma unroll
    for (int o = 16; o > 0; o >>= 1)
        term += __shfl_down_sync(0xffffffffu, term, o);

    __shared__ double sAcc[8];
    if ((tid & 31) == 0) sAcc[tid >> 5] = term;
    __syncthreads();
    if (tid == 0) {
        double t = 0.0;
#pragma unroll
        for (int w = 0; w < 8; w++) t += sAcc[w];
        atomicAdd(&g_acc, t);
        __threadfence();
        unsigned int done = atomicAdd(&g_counter, 1u);
        if (done == NBLOCKS - 1) {
            out[0] = (float)g_acc;
            g_acc = 0.0;
            g_counter = 0u;
        }
    }
}

extern "C" void kernel_launch(void* const* d_in, const int* in_sizes, int n_in,
                              void* d_out, int out_size) {
    const float* tpl = (const float*)d_in[0];   // batch_pauli_tensor [N,Q,P] f32
    const float* cf  = (const float*)d_in[1];   // batch_coeff [N]
    const float* hp  = (const float*)d_in[2];   // heads_param [S,Q,P]
    const float* hrp = (const float*)d_in[3];   // head_ratios_param [S]

    cudaFuncSetAttribute(cov_kernel, cudaFuncAttributeMaxDynamicSharedMemorySize,
                         SMEM_FLOATS * sizeof(float));

    setup_kernel<<<13, 256>>>(hp, hrp);
    cov_kernel<<<NBLOCKS, 256, SMEM_FLOATS * sizeof(float)>>>(tpl, cf, (float*)d_out);
}

// round 14
// speedup vs baseline: 1.0439x; 1.0439x over previous
#include <cuda_runtime.h>

#define NWORDS 100000
#define NQ 50
#define NS 64
#define NBLOCKS 782   // ceil(100000 / 128)

// Heads table, padded octant layout: per (q, qt) cell of 28 floats (112B stride)
__device__ __align__(16) float g_hH[NQ * 8 * 28];
__device__ __align__(8)  float g_hr[NS];
__device__ double g_acc = 0.0;
__device__ unsigned int g_counter = 0u;

typedef unsigned long long u64;

__device__ __forceinline__ u64 bc2(float x) {
    u64 r; asm("mov.b64 %0, {%1, %1};" : "=l"(r) : "f"(x)); return r;
}
__device__ __forceinline__ u64 fma2(u64 a, u64 b, u64 c) {
    u64 d; asm("fma.rn.f32x2 %0, %1, %2, %3;" : "=l"(d) : "l"(a), "l"(b), "l"(c)); return d;
}
__device__ __forceinline__ u64 mul2(u64 a, u64 b) {
    u64 d; asm("mul.rn.f32x2 %0, %1, %2;" : "=l"(d) : "l"(a), "l"(b)); return d;
}
__device__ __forceinline__ void up2(u64 a, float& x, float& y) {
    asm("mov.b64 {%0, %1}, %2;" : "=f"(x), "=f"(y) : "l"(a));
}

__device__ __forceinline__ float sp20(float x) {
    float y = 20.0f * x;
    return fmaxf(y, 0.0f) + log1pf(expf(-fabsf(y)));
}

__global__ void setup_kernel(const float* __restrict__ hp, const float* __restrict__ hrp) {
    int tid = threadIdx.x;
    if (blockIdx.x == 0) {
        __shared__ float sv[NS];
        __shared__ float ssum;
        if (tid < NS) sv[tid] = sp20(hrp[tid]);
        __syncthreads();
        if (tid == 0) {
            float s = 0.0f;
            for (int i = 0; i < NS; i++) s += sv[i];
            ssum = fmaxf(s, 1e-12f);
        }
        __syncthreads();
        if (tid < NS) g_hr[tid] = (sv[tid] / ssum + 0.001f / (float)NS) / 1.001f;
    }
    int idx = blockIdx.x * blockDim.x + tid;
    if (idx < NS * NQ) {
        int q = idx >> 6;
        int s = idx & 63;
        const float* p = hp + ((size_t)s * NQ + q) * 3;
        float v0 = sp20(p[0]);
        float v1 = sp20(p[1]);
        float v2 = sp20(p[2]);
        float sm = fmaxf((v0 + v1) + v2, 1e-12f);
        int qt = s >> 3, j = (s >> 2) & 1, r = s & 3;
        float* g = g_hH + ((size_t)q * 8 + qt) * 28 + j * 12;
        g[r]     = v0 / sm;
        g[4 + r] = v1 / sm;
        g[8 + r] = v2 / sm;
    }
}

// Thread = (n-quad, s-octant). 256 threads -> 32 n-quads (128 n) x 8 s-octants.
// smem: heads 11200 f (44.8KB) + tile 30 rows x pitch 164 (+row swizzle, fits 28+127<164)
#define SH_HEADS 11200
#define SH_TROW  164
#define SH_TILE  (30 * SH_TROW + 32)
#define SMEM_FLOATS (SH_HEADS + SH_TILE)

// per-row 16B swizzle keeps staging STS ~2-way instead of 4-way:
#define TROW_OFF(r) ((r) * SH_TROW + 4 * (((r) >> 1) & 7))

__global__ __launch_bounds__(256, 3)
void cov_kernel(const float* __restrict__ tpl, const float* __restrict__ coeff,
                float* __restrict__ out) {
    extern __shared__ __align__(16) float smem[];
    float* sH = smem;
    float* sT = smem + SH_HEADS;

    const int tid   = threadIdx.x;
    const int qt    = tid & 7;          // s-octant 0..7 (8 heads each)
    const int nq    = tid >> 3;         // n-quad 0..31
    const int nBase = blockIdx.x * 128;

    // stage heads table (44.8 KB) once per block
    {
        const float4* src = (const float4*)g_hH;
        float4* dst = (float4*)sH;
        for (int i = tid; i < SH_HEADS / 4; i += 256) dst[i] = src[i];
    }

    const u64 ONE = 0x3f8000003f800000ULL;
    u64 prod[4][4];
#pragma unroll
    for (int p = 0; p < 4; p++)
#pragma unroll
        for (int n = 0; n < 4; n++) prod[p][n] = ONE;

#pragma unroll 1
    for (int qc = 0; qc < NQ; qc += 10) {
        __syncthreads();   // heads staging (1st iter) / sT reuse
        // stage 128 rows x 30 floats (coalesced float2) -> transposed, swizzled sT
        for (int i = tid; i < 128 * 15; i += 256) {
            int nl = i / 15;
            int j2 = i - nl * 15;
            int n  = nBase + nl;
            n = (n < NWORDS) ? n : (NWORDS - 1);
            float2 v = *(const float2*)(tpl + (size_t)n * (NQ * 3) + (size_t)(qc * 3 + j2 * 2));
            int jj = j2 * 2;
            int sw = 4 * (j2 & 7);
            sT[jj * SH_TROW + sw + nl]       = v.x;
            sT[(jj + 1) * SH_TROW + sw + nl] = v.y;
        }
        __syncthreads();

#pragma unroll 2
        for (int qq = 0; qq < 10; qq++) {
            // conflict-free heads cell (112B stride across octant lanes)
            const ulonglong2* hb =
                (const ulonglong2*)(sH + ((size_t)(qc + qq) * 8 + qt) * 28);
            ulonglong2 A0 = hb[0], B0 = hb[1], C0 = hb[2];
            ulonglong2 A1 = hb[3], B1 = hb[4], C1 = hb[5];

            int r0i = qq * 3;
            float4 r0 = *(const float4*)(sT + TROW_OFF(r0i)     + nq * 4);
            float4 r1 = *(const float4*)(sT + TROW_OFF(r0i + 1) + nq * 4);
            float4 r2 = *(const float4*)(sT + TROW_OFF(r0i + 2) + nq * 4);
            u64 T0[4], T1[4], T2[4];
            T0[0] = bc2(r0.x); T0[1] = bc2(r0.y); T0[2] = bc2(r0.z); T0[3] = bc2(r0.w);
            T1[0] = bc2(r1.x); T1[1] = bc2(r1.y); T1[2] = bc2(r1.z); T1[3] = bc2(r1.w);
            T2[0] = bc2(r2.x); T2[1] = bc2(r2.y); T2[2] = bc2(r2.z); T2[3] = bc2(r2.w);

#pragma unroll
            for (int n = 0; n < 4; n++) {
                u64 a = mul2(C0.x, T2[n]);
                a = fma2(B0.x, T1[n], a);
                a = fma2(A0.x, T0[n], a);
                prod[0][n] = mul2(prod[0][n], a);
                u64 b = mul2(C0.y, T2[n]);
                b = fma2(B0.y, T1[n], b);
                b = fma2(A0.y, T0[n], b);
                prod[1][n] = mul2(prod[1][n], b);
                u64 c = mul2(C1.x, T2[n]);
                c = fma2(B1.x, T1[n], c);
                c = fma2(A1.x, T0[n], c);
                prod[2][n] = mul2(prod[2][n], c);
                u64 d = mul2(C1.y, T2[n]);
                d = fma2(B1.y, T1[n], d);
                d = fma2(A1.y, T0[n], d);
                prod[3][n] = mul2(prod[3][n], d);
            }
        }
    }

    // ratio-weighted partial covs for this thread's 4 n over its 8 heads
    float cov[4] = {0.f, 0.f, 0.f, 0.f};
#pragma unroll
    for (int p = 0; p < 4; p++) {
        float2 w = *(const float2*)(g_hr + (size_t)qt * 8 + p * 2);
#pragma unroll
        for (int n = 0; n < 4; n++) {
            float lo, hi;
            up2(prod[p][n], lo, hi);
            cov[n] = fmaf(w.x, lo, cov[n]);
            cov[n] = fmaf(w.y, hi, cov[n]);
        }
    }
    // combine the 8 s-octants (8 consecutive lanes share an n-quad)
#pragma unroll
    for (int o = 1; o <= 4; o <<= 1)
#pragma unroll
        for (int n = 0; n < 4; n++)
            cov[n] += __shfl_xor_sync(0xffffffffu, cov[n], o);

    double term = 0.0;
    if (qt == 0) {
        int n0 = nBase + nq * 4;
#pragma unroll
        for (int k = 0; k < 4; k++) {
            if (n0 + k < NWORDS) {
                float c = coeff[n0 + k];
                term += ((double)c * (double)c) / (double)cov[k];
            }
        }
    }
#pragma unroll
    for (int o = 16; o > 0; o >>= 1)
        term += __shfl_down_sync(0xffffffffu, term, o);

    __shared__ double sAcc[8];
    if ((tid & 31) == 0) sAcc[tid >> 5] = term;
    __syncthreads();
    if (tid == 0) {
        double t = 0.0;
#pragma unroll
        for (int w = 0; w < 8; w++) t += sAcc[w];
        atomicAdd(&g_acc, t);
        __threadfence();
        unsigned int done = atomicAdd(&g_counter, 1u);
        if (done == NBLOCKS - 1) {
            out[0] = (float)g_acc;
            g_acc = 0.0;
            g_counter = 0u;
        }
    }
}

extern "C" void kernel_launch(void* const* d_in, const int* in_sizes, int n_in,
                              void* d_out, int out_size) {
    const float* tpl = (const float*)d_in[0];   // batch_pauli_tensor [N,Q,P] f32
    const float* cf  = (const float*)d_in[1];   // batch_coeff [N]
    const float* hp  = (const float*)d_in[2];   // heads_param [S,Q,P]
    const float* hrp = (const float*)d_in[3];   // head_ratios_param [S]

    cudaFuncSetAttribute(cov_kernel, cudaFuncAttributeMaxDynamicSharedMemorySize,
                         SMEM_FLOATS * sizeof(float));

    setup_kernel<<<13, 256>>>(hp, hrp);
    cov_kernel<<<NBLOCKS, 256, SMEM_FLOATS * sizeof(float)>>>(tpl, cf, (float*)d_out);
}